// round 5
// baseline (speedup 1.0000x reference)
#include <cuda_runtime.h>

#define T_STEPS 512
#define BATCH   64
#define IDIM    128
#define HDIM    512
#define ZDIM    32
#define GRID_MAIN 128
#define ALPHA 0.2f
#define ONEMA 0.8f

// ---------------- device scratch (static globals; no runtime allocation) ----
__device__ float g_xin [(size_t)T_STEPS * HDIM * BATCH];        // (t, g, b): x@W_in^T + b_rec
__device__ float g_rbuf[(size_t)(T_STEPS + 1) * HDIM * BATCH];  // (t, h, b): tanh(v_t)
__device__ float g_xz  [(size_t)T_STEPS * BATCH * ZDIM];        // (t, b, z): x@B_z^T + b_zz
__device__ float g_sbuf[(size_t)T_STEPS * BATCH * 2];           // (t, b, k): s - 0.5
__device__ unsigned long long g_bar;                            // monotonic barrier counter

// ---------------- helpers ---------------------------------------------------
__device__ __forceinline__ unsigned smem_u32(const void* p) {
    return (unsigned)__cvta_generic_to_shared(p);
}
__device__ __forceinline__ void cp16(unsigned dst, const void* src) {
    asm volatile("cp.async.cg.shared.global [%0], [%1], 16;" :: "r"(dst), "l"(src));
}
__device__ __forceinline__ void cp_commit() {
    asm volatile("cp.async.commit_group;");
}
template <int N>
__device__ __forceinline__ void cp_wait() {
    asm volatile("cp.async.wait_group %0;" :: "n"(N));
}

// Replay-safe grid barrier: monotonic counter, target derived from arrival slot.
__device__ __forceinline__ void grid_barrier() {
    __syncthreads();
    if (threadIdx.x == 0) {
        __threadfence();  // release our r writes
        unsigned long long a = atomicAdd(&g_bar, 1ULL);
        unsigned long long target = (a / GRID_MAIN + 1ULL) * (unsigned long long)GRID_MAIN;
        unsigned long long cur;
        do {
            asm volatile("ld.global.acquire.gpu.u64 %0, [%1];" : "=l"(cur) : "l"(&g_bar));
        } while (cur < target);
    }
    __syncthreads();
}

// ---------------- k_xin: xin[t,g,b] = sum_i x[b,t,i]*W_in[g,i] + b_rec[g] ----
// grid (T, H/64), 128 threads, 64KB dyn smem
__global__ void __launch_bounds__(128, 1) k_xin(const float* __restrict__ x,
                                                const float* __restrict__ win,
                                                const float* __restrict__ brec) {
    extern __shared__ float sm[];
    float* x_s = sm;         // [i][b]  128*64
    float* w_s = sm + 8192;  // [i][gl] 128*64
    const int tid = threadIdx.x;
    const int t   = blockIdx.x;
    const int g0  = blockIdx.y * 64;

    for (int idx = tid; idx < 8192; idx += 128) {
        int b = idx >> 7, i = idx & 127;
        x_s[i * 64 + b] = x[(size_t)b * (T_STEPS * IDIM) + t * IDIM + i];
    }
    for (int idx = tid; idx < 8192; idx += 128) {
        int gl = idx >> 7, i = idx & 127;
        w_s[i * 64 + gl] = win[(g0 + gl) * IDIM + i];
    }
    __syncthreads();

    const int gt = tid >> 3;   // 0..15 (4 g each)
    const int bt = tid & 7;    // 0..7  (8 b each)
    float acc[4][8];
#pragma unroll
    for (int a = 0; a < 4; ++a)
#pragma unroll
        for (int j = 0; j < 8; ++j) acc[a][j] = 0.f;

    const float4* wp = (const float4*)w_s + gt;
    const float4* xp = (const float4*)x_s + bt * 2;
#pragma unroll 4
    for (int i = 0; i < 128; ++i) {
        float4 wv = wp[i * 16];
        float4 xa = xp[i * 16];
        float4 xb = xp[i * 16 + 1];
        float xv[8] = {xa.x, xa.y, xa.z, xa.w, xb.x, xb.y, xb.z, xb.w};
#pragma unroll
        for (int j = 0; j < 8; ++j) {
            acc[0][j] = fmaf(wv.x, xv[j], acc[0][j]);
            acc[1][j] = fmaf(wv.y, xv[j], acc[1][j]);
            acc[2][j] = fmaf(wv.z, xv[j], acc[2][j]);
            acc[3][j] = fmaf(wv.w, xv[j], acc[3][j]);
        }
    }
#pragma unroll
    for (int a = 0; a < 4; ++a) {
        int g = g0 + gt * 4 + a;
        float bias = brec[g];
#pragma unroll
        for (int j = 0; j < 8; ++j) {
            int b = bt * 8 + j;
            g_xin[(size_t)t * (HDIM * BATCH) + g * BATCH + b] = acc[a][j] + bias;
        }
    }
}

// ---------------- k_xz: xz[t,b,z] = sum_i x[b,t,i]*B_z[z,i] + b_zz[z] -------
// grid (T), 64 threads, 48KB dyn smem
__global__ void __launch_bounds__(64, 1) k_xz(const float* __restrict__ x,
                                              const float* __restrict__ Bz,
                                              const float* __restrict__ bzz) {
    extern __shared__ float sm[];
    float* x_s  = sm;         // [i][b]  128*64
    float* bz_s = sm + 8192;  // [i][z]  128*32
    const int tid = threadIdx.x;
    const int t   = blockIdx.x;

    for (int idx = tid; idx < 8192; idx += 64) {
        int b = idx >> 7, i = idx & 127;
        x_s[i * 64 + b] = x[(size_t)b * (T_STEPS * IDIM) + t * IDIM + i];
    }
    for (int idx = tid; idx < 4096; idx += 64) {
        int z = idx >> 7, i = idx & 127;
        bz_s[i * 32 + z] = Bz[z * IDIM + i];
    }
    __syncthreads();

    const int zt = tid >> 3;  // 0..7 (4 z each)
    const int bt = tid & 7;   // 0..7 (8 b each)
    float acc[4][8];
#pragma unroll
    for (int a = 0; a < 4; ++a)
#pragma unroll
        for (int j = 0; j < 8; ++j) acc[a][j] = 0.f;

    const float4* wp = (const float4*)bz_s + zt;
    const float4* xp = (const float4*)x_s + bt * 2;
#pragma unroll 4
    for (int i = 0; i < 128; ++i) {
        float4 wv = wp[i * 8];
        float4 xa = xp[i * 16];
        float4 xb = xp[i * 16 + 1];
        float xv[8] = {xa.x, xa.y, xa.z, xa.w, xb.x, xb.y, xb.z, xb.w};
#pragma unroll
        for (int j = 0; j < 8; ++j) {
            acc[0][j] = fmaf(wv.x, xv[j], acc[0][j]);
            acc[1][j] = fmaf(wv.y, xv[j], acc[1][j]);
            acc[2][j] = fmaf(wv.z, xv[j], acc[2][j]);
            acc[3][j] = fmaf(wv.w, xv[j], acc[3][j]);
        }
    }
#pragma unroll
    for (int a = 0; a < 4; ++a) {
        int z = zt * 4 + a;
        float bias = bzz[z];
#pragma unroll
        for (int j = 0; j < 8; ++j) {
            int b = bt * 8 + j;
            g_xz[(size_t)t * (BATCH * ZDIM) + b * ZDIM + z] = acc[a][j] + bias;
        }
    }
}

// ---------------- k_zscan: sequential z recursion, emits (s-0.5) ------------
// grid (B=64), 32 threads
__global__ void k_zscan(const float* __restrict__ Wzz,
                        const float* __restrict__ M,
                        const float* __restrict__ c,
                        float* __restrict__ dout, int out_size) {
    __shared__ float wzz_s[ZDIM * ZDIM];  // transposed: [j][i]
    __shared__ float fzs[ZDIM];
    const int i = threadIdx.x;
    const int b = blockIdx.x;

    for (int idx = i; idx < ZDIM * ZDIM; idx += 32) {
        int is = idx >> 5, j = idx & 31;
        wzz_s[j * 32 + is] = Wzz[idx];  // Wzz[is][j] -> [j][is]
    }
    float m0 = M[i], m1 = M[ZDIM + i];
    float c0 = c[0], c1 = c[1];
    float z = 0.f;
    __syncwarp();

    for (int t = 0; t < T_STEPS; ++t) {
        fzs[i] = tanhf(z);
        __syncwarp();
        float a = 0.f;
#pragma unroll 8
        for (int j = 0; j < 32; ++j) a = fmaf(wzz_s[j * 32 + i], fzs[j], a);
        __syncwarp();
        z = ONEMA * z + ALPHA * (a + g_xz[(size_t)t * (BATCH * ZDIM) + b * ZDIM + i]);
        float p0 = m0 * z, p1 = m1 * z;
#pragma unroll
        for (int off = 16; off; off >>= 1) {
            p0 += __shfl_xor_sync(0xffffffffu, p0, off);
            p1 += __shfl_xor_sync(0xffffffffu, p1, off);
        }
        if (i == 0) {
            size_t o = ((size_t)t * BATCH + b) * 2;
            g_sbuf[o + 0] = 1.f / (1.f + expf(-(p0 + c0))) - 0.5f;
            g_sbuf[o + 1] = 1.f / (1.f + expf(-(p1 + c1))) - 0.5f;
        }
    }
    if (out_size >= BATCH * T_STEPS + BATCH * HDIM + BATCH * ZDIM)
        dout[BATCH * T_STEPS + BATCH * HDIM + b * ZDIM + i] = z;  // zT
}

// ---------------- k_main: persistent recurrent core -------------------------
// grid 128, 256 threads, dyn smem = 47368 floats (189,472 B)
// SMEM: r_s[512*64] | w_s[512*16] | part[256*24] | v_s[256] | u_s[8]
__global__ void __launch_bounds__(256, 1) k_main(const float* __restrict__ W,
                                                 const float* __restrict__ V,
                                                 const float* __restrict__ U,
                                                 float* __restrict__ dout,
                                                 int out_size) {
    extern __shared__ float sm[];
    float* r_s  = sm;             // [h][b]
    float* w_s  = sm + 32768;     // [h][gl*4 + m], m=3 is pad
    float* part = sm + 40960;     // [tid][24]
    float* v_s  = sm + 47104;     // [gl*64 + b]
    float* u_s  = sm + 47360;     // [gl*2 + k]
    const int tid = threadIdx.x;
    const int g0  = blockIdx.x * 4;

    // stage weights: W0 = W, W1 = W*V0, W2 = W*V1 for our 4 rows
    for (int idx = tid; idx < HDIM * 12; idx += 256) {
        int h = idx / 12, rem = idx % 12, gl = rem / 3, m = rem % 3;
        float wv = W[(g0 + gl) * HDIM + h];
        if (m) wv *= V[h * 2 + (m - 1)];
        w_s[h * 16 + gl * 4 + m] = wv;
    }
    for (int idx = tid; idx < HDIM * 4; idx += 256)
        w_s[(idx >> 2) * 16 + (idx & 3) * 4 + 3] = 0.f;
    if (tid < 8) u_s[tid] = U[(g0 + (tid >> 1)) * 2 + (tid & 1)];
    v_s[tid] = 0.f;
    // zero our slice of r_0 = tanh(0)
    g_rbuf[(size_t)(g0 + (tid >> 6)) * BATCH + (tid & 63)] = 0.f;
    grid_barrier();

    const int hs = tid >> 5;        // h-slice 0..7
    const int gl = (tid >> 3) & 3;  // 0..3
    const int bg = tid & 7;         // batch group (8 batches)
    const unsigned rbase = smem_u32(r_s);

    for (int t = 0; t < T_STEPS; ++t) {
        // prefetch r_t in 4 chunks of 32KB (linear copy, layouts identical)
        const float* rg = g_rbuf + (size_t)t * (HDIM * BATCH);
#pragma unroll
        for (int ch = 0; ch < 4; ++ch) {
#pragma unroll
            for (int k = 0; k < 8; ++k) {
                int idx4 = ch * 2048 + k * 256 + tid;
                cp16(rbase + idx4 * 16, rg + idx4 * 4);
            }
            cp_commit();
        }

        float acc[3][8];
#pragma unroll
        for (int m = 0; m < 3; ++m)
#pragma unroll
            for (int j = 0; j < 8; ++j) acc[m][j] = 0.f;

#pragma unroll
        for (int ch = 0; ch < 4; ++ch) {
            if (ch == 0) cp_wait<3>();
            else if (ch == 1) cp_wait<2>();
            else if (ch == 2) cp_wait<1>();
            else cp_wait<0>();
            __syncthreads();
            int hstart = ch * 128 + hs * 16;
            const float4* wp = (const float4*)w_s + hstart * 4 + gl;
            const float4* rp = (const float4*)r_s + hstart * 16 + bg * 2;
#pragma unroll
            for (int ii = 0; ii < 16; ++ii) {
                float4 wv = wp[ii * 4];
                float4 ra = rp[ii * 16];
                float4 rb = rp[ii * 16 + 1];
                float rv[8] = {ra.x, ra.y, ra.z, ra.w, rb.x, rb.y, rb.z, rb.w};
#pragma unroll
                for (int j = 0; j < 8; ++j) {
                    acc[0][j] = fmaf(wv.x, rv[j], acc[0][j]);
                    acc[1][j] = fmaf(wv.y, rv[j], acc[1][j]);
                    acc[2][j] = fmaf(wv.z, rv[j], acc[2][j]);
                }
            }
        }

        // write partials, reduce over 8 h-slices, epilogue
#pragma unroll
        for (int m = 0; m < 3; ++m)
#pragma unroll
            for (int j = 0; j < 8; ++j) part[tid * 24 + m * 8 + j] = acc[m][j];
        __syncthreads();
        {
            const int egl = tid >> 6;
            const int b   = tid & 63;
            const int ebg = b >> 3, ebi = b & 7;
            float y0 = 0.f, y1 = 0.f, y2 = 0.f;
#pragma unroll
            for (int h2 = 0; h2 < 8; ++h2) {
                int base = (h2 * 32 + egl * 8 + ebg) * 24 + ebi;
                y0 += part[base];
                y1 += part[base + 8];
                y2 += part[base + 16];
            }
            const float* sp = g_sbuf + ((size_t)t * BATCH + b) * 2;
            float s0 = sp[0], s1 = sp[1];
            float xi = g_xin[(size_t)t * (HDIM * BATCH) + (g0 + egl) * BATCH + b];
            float v = v_s[tid];
            v = ONEMA * v +
                ALPHA * (y0 + s0 * u_s[egl * 2] * y1 + s1 * u_s[egl * 2 + 1] * y2 + xi);
            v_s[tid] = v;
            float r = tanhf(v);
            g_rbuf[(size_t)(t + 1) * (HDIM * BATCH) + (g0 + egl) * BATCH + b] = r;
            if (t == T_STEPS - 1 && out_size >= BATCH * T_STEPS + BATCH * HDIM)
                dout[BATCH * T_STEPS + b * HDIM + (g0 + egl)] = v;  // vT
        }
        grid_barrier();
    }
}

// ---------------- k_out: y[b,t] = tanh(v_{t+1}) @ w_out + b_out -------------
// grid 128, 256 threads
__global__ void __launch_bounds__(256, 1) k_out(const float* __restrict__ wout,
                                                const float* __restrict__ bout,
                                                float* __restrict__ dout,
                                                int out_size) {
    __shared__ float w_sh[HDIM];
    const int tid = threadIdx.x;
    w_sh[tid] = wout[tid];
    w_sh[tid + 256] = wout[tid + 256];
    __syncthreads();
    int gid = blockIdx.x * 256 + tid;
    int b = gid & 63, t = gid >> 6;
    const float* rp = g_rbuf + (size_t)(t + 1) * (HDIM * BATCH) + b;
    float acc = bout[0];
#pragma unroll 8
    for (int g = 0; g < HDIM; ++g) acc = fmaf(rp[g * BATCH], w_sh[g], acc);
    int o = b * T_STEPS + t;
    if (o < out_size) dout[o] = acc;
}

// ---------------- launch -----------------------------------------------------
extern "C" void kernel_launch(void* const* d_in, const int* in_sizes, int n_in,
                              void* d_out, int out_size) {
    const float* x    = (const float*)d_in[0];
    const float* win  = (const float*)d_in[1];
    const float* wrec = (const float*)d_in[2];
    const float* brec = (const float*)d_in[3];
    const float* wout = (const float*)d_in[4];
    const float* bout = (const float*)d_in[5];
    const float* wzz  = (const float*)d_in[6];
    const float* bzz  = (const float*)d_in[7];
    const float* Bz   = (const float*)d_in[8];
    const float* M    = (const float*)d_in[9];
    const float* c    = (const float*)d_in[10];
    const float* U    = (const float*)d_in[11];
    const float* V    = (const float*)d_in[12];
    float* out = (float*)d_out;

    cudaFuncSetAttribute(k_xin,  cudaFuncAttributeMaxDynamicSharedMemorySize, 16384 * 4);
    cudaFuncSetAttribute(k_xz,   cudaFuncAttributeMaxDynamicSharedMemorySize, 12288 * 4);
    cudaFuncSetAttribute(k_main, cudaFuncAttributeMaxDynamicSharedMemorySize, 47368 * 4);

    k_xin<<<dim3(T_STEPS, HDIM / 64), 128, 16384 * 4>>>(x, win, brec);
    k_xz<<<T_STEPS, 64, 12288 * 4>>>(x, Bz, bzz);
    k_zscan<<<BATCH, 32>>>(wzz, M, c, out, out_size);
    k_main<<<GRID_MAIN, 256, 47368 * 4>>>(wrec, V, U, out, out_size);
    k_out<<<(BATCH * T_STEPS) / 256, 256>>>(wout, bout, out, out_size);
}

// round 6
// speedup vs baseline: 1.3604x; 1.3604x over previous
#include <cuda_runtime.h>

#define T_STEPS 512
#define BATCH   64
#define IDIM    128
#define HDIM    512
#define ZDIM    32
#define GRID_MAIN 128
#define ALPHA 0.2f
#define ONEMA 0.8f

typedef unsigned long long ull;

// ---------------- device scratch (static globals; no runtime allocation) ----
__device__ float g_xin [(size_t)T_STEPS * HDIM * BATCH];        // (t, g, b)
__device__ float g_rbuf[(size_t)(T_STEPS + 1) * HDIM * BATCH];  // (t, h, b)
__device__ float g_xz  [(size_t)T_STEPS * BATCH * ZDIM];        // (t, b, z)
__device__ float g_sbuf[(size_t)T_STEPS * BATCH * 2];           // (t, b, k): s-0.5
__device__ unsigned long long g_bar;                            // monotonic barrier

// ---------------- helpers ---------------------------------------------------
__device__ __forceinline__ unsigned smem_u32(const void* p) {
    return (unsigned)__cvta_generic_to_shared(p);
}
__device__ __forceinline__ void cp16(unsigned dst, const void* src) {
    asm volatile("cp.async.cg.shared.global [%0], [%1], 16;" :: "r"(dst), "l"(src));
}
__device__ __forceinline__ void cp_commit() {
    asm volatile("cp.async.commit_group;");
}
template <int N>
__device__ __forceinline__ void cp_wait() {
    asm volatile("cp.async.wait_group %0;" :: "n"(N));
}
// packed fp32x2 math (sm_100+): 2 FMA lanes per instruction
__device__ __forceinline__ ull ffma2(ull a, ull b, ull c) {
    ull d; asm("fma.rn.f32x2 %0,%1,%2,%3;" : "=l"(d) : "l"(a), "l"(b), "l"(c)); return d;
}
__device__ __forceinline__ ull fmul2(ull a, ull b) {
    ull d; asm("mul.rn.f32x2 %0,%1,%2;" : "=l"(d) : "l"(a), "l"(b)); return d;
}
__device__ __forceinline__ ull fadd2(ull a, ull b) {
    ull d; asm("add.rn.f32x2 %0,%1,%2;" : "=l"(d) : "l"(a), "l"(b)); return d;
}
__device__ __forceinline__ ull dup2(float x) {
    ull d; asm("mov.b64 %0,{%1,%1};" : "=l"(d) : "f"(x)); return d;
}

// Replay-safe grid barrier: monotonic counter, target derived from arrival slot.
__device__ __forceinline__ void grid_barrier() {
    __syncthreads();
    if (threadIdx.x == 0) {
        __threadfence();
        unsigned long long a = atomicAdd(&g_bar, 1ULL);
        unsigned long long target = (a / GRID_MAIN + 1ULL) * (unsigned long long)GRID_MAIN;
        unsigned long long cur;
        do {
            asm volatile("ld.global.acquire.gpu.u64 %0, [%1];" : "=l"(cur) : "l"(&g_bar));
        } while (cur < target);
    }
    __syncthreads();
}

// ---------------- k_xin: xin[t,g,b] = sum_i x[b,t,i]*W_in[g,i] + b_rec[g] ----
__global__ void __launch_bounds__(128, 1) k_xin(const float* __restrict__ x,
                                                const float* __restrict__ win,
                                                const float* __restrict__ brec) {
    extern __shared__ float sm[];
    float* x_s = sm;         // [i][b]
    float* w_s = sm + 8192;  // [i][gl]
    const int tid = threadIdx.x;
    const int t   = blockIdx.x;
    const int g0  = blockIdx.y * 64;

    for (int idx = tid; idx < 8192; idx += 128) {
        int b = idx >> 7, i = idx & 127;
        x_s[i * 64 + b] = x[(size_t)b * (T_STEPS * IDIM) + t * IDIM + i];
    }
    for (int idx = tid; idx < 8192; idx += 128) {
        int gl = idx >> 7, i = idx & 127;
        w_s[i * 64 + gl] = win[(g0 + gl) * IDIM + i];
    }
    __syncthreads();

    const int gt = tid >> 3;
    const int bt = tid & 7;
    float acc[4][8];
#pragma unroll
    for (int a = 0; a < 4; ++a)
#pragma unroll
        for (int j = 0; j < 8; ++j) acc[a][j] = 0.f;

    const float4* wp = (const float4*)w_s + gt;
    const float4* xp = (const float4*)x_s + bt * 2;
#pragma unroll 4
    for (int i = 0; i < 128; ++i) {
        float4 wv = wp[i * 16];
        float4 xa = xp[i * 16];
        float4 xb = xp[i * 16 + 1];
        float xv[8] = {xa.x, xa.y, xa.z, xa.w, xb.x, xb.y, xb.z, xb.w};
#pragma unroll
        for (int j = 0; j < 8; ++j) {
            acc[0][j] = fmaf(wv.x, xv[j], acc[0][j]);
            acc[1][j] = fmaf(wv.y, xv[j], acc[1][j]);
            acc[2][j] = fmaf(wv.z, xv[j], acc[2][j]);
            acc[3][j] = fmaf(wv.w, xv[j], acc[3][j]);
        }
    }
#pragma unroll
    for (int a = 0; a < 4; ++a) {
        int g = g0 + gt * 4 + a;
        float bias = brec[g];
#pragma unroll
        for (int j = 0; j < 8; ++j) {
            int b = bt * 8 + j;
            g_xin[(size_t)t * (HDIM * BATCH) + g * BATCH + b] = acc[a][j] + bias;
        }
    }
}

// ---------------- k_xz: xz[t,b,z] = sum_i x[b,t,i]*B_z[z,i] + b_zz[z] -------
__global__ void __launch_bounds__(64, 1) k_xz(const float* __restrict__ x,
                                              const float* __restrict__ Bz,
                                              const float* __restrict__ bzz) {
    extern __shared__ float sm[];
    float* x_s  = sm;         // [i][b]
    float* bz_s = sm + 8192;  // [i][z]
    const int tid = threadIdx.x;
    const int t   = blockIdx.x;

    for (int idx = tid; idx < 8192; idx += 64) {
        int b = idx >> 7, i = idx & 127;
        x_s[i * 64 + b] = x[(size_t)b * (T_STEPS * IDIM) + t * IDIM + i];
    }
    for (int idx = tid; idx < 4096; idx += 64) {
        int z = idx >> 7, i = idx & 127;
        bz_s[i * 32 + z] = Bz[z * IDIM + i];
    }
    __syncthreads();

    const int zt = tid >> 3;
    const int bt = tid & 7;
    float acc[4][8];
#pragma unroll
    for (int a = 0; a < 4; ++a)
#pragma unroll
        for (int j = 0; j < 8; ++j) acc[a][j] = 0.f;

    const float4* wp = (const float4*)bz_s + zt;
    const float4* xp = (const float4*)x_s + bt * 2;
#pragma unroll 4
    for (int i = 0; i < 128; ++i) {
        float4 wv = wp[i * 8];
        float4 xa = xp[i * 16];
        float4 xb = xp[i * 16 + 1];
        float xv[8] = {xa.x, xa.y, xa.z, xa.w, xb.x, xb.y, xb.z, xb.w};
#pragma unroll
        for (int j = 0; j < 8; ++j) {
            acc[0][j] = fmaf(wv.x, xv[j], acc[0][j]);
            acc[1][j] = fmaf(wv.y, xv[j], acc[1][j]);
            acc[2][j] = fmaf(wv.z, xv[j], acc[2][j]);
            acc[3][j] = fmaf(wv.w, xv[j], acc[3][j]);
        }
    }
#pragma unroll
    for (int a = 0; a < 4; ++a) {
        int z = zt * 4 + a;
        float bias = bzz[z];
#pragma unroll
        for (int j = 0; j < 8; ++j) {
            int b = bt * 8 + j;
            g_xz[(size_t)t * (BATCH * ZDIM) + b * ZDIM + z] = acc[a][j] + bias;
        }
    }
}

// ---------------- k_zscan: sequential z recursion, emits (s-0.5) ------------
__global__ void k_zscan(const float* __restrict__ Wzz,
                        const float* __restrict__ M,
                        const float* __restrict__ c,
                        float* __restrict__ dout, int out_size) {
    __shared__ float wzz_s[ZDIM * ZDIM];  // transposed [j][i]
    __shared__ float fzs[ZDIM];
    const int i = threadIdx.x;
    const int b = blockIdx.x;

    for (int idx = i; idx < ZDIM * ZDIM; idx += 32) {
        int is = idx >> 5, j = idx & 31;
        wzz_s[j * 32 + is] = Wzz[idx];
    }
    float m0 = M[i], m1 = M[ZDIM + i];
    float c0 = c[0], c1 = c[1];
    float z = 0.f;
    __syncwarp();

    for (int t = 0; t < T_STEPS; ++t) {
        fzs[i] = tanhf(z);
        __syncwarp();
        float a = 0.f;
#pragma unroll 8
        for (int j = 0; j < 32; ++j) a = fmaf(wzz_s[j * 32 + i], fzs[j], a);
        __syncwarp();
        z = ONEMA * z + ALPHA * (a + g_xz[(size_t)t * (BATCH * ZDIM) + b * ZDIM + i]);
        float p0 = m0 * z, p1 = m1 * z;
#pragma unroll
        for (int off = 16; off; off >>= 1) {
            p0 += __shfl_xor_sync(0xffffffffu, p0, off);
            p1 += __shfl_xor_sync(0xffffffffu, p1, off);
        }
        if (i == 0) {
            size_t o = ((size_t)t * BATCH + b) * 2;
            g_sbuf[o + 0] = 1.f / (1.f + expf(-(p0 + c0))) - 0.5f;
            g_sbuf[o + 1] = 1.f / (1.f + expf(-(p1 + c1))) - 0.5f;
        }
    }
    if (out_size >= BATCH * T_STEPS + BATCH * HDIM + BATCH * ZDIM)
        dout[BATCH * T_STEPS + BATCH * HDIM + b * ZDIM + i] = z;  // zT
}

// ---------------- k_main: persistent recurrent core (f32x2, 12x8 tiles) -----
// grid 128, 256 threads, dyn smem = 45824 floats (183,296 B)
// SMEM: r ring 2x[128h][64b] | w_s[512h][8] (w0..w3,v0,v1,pad) |
//       part[32 slice][12 row][64 b] | y_s[12][64]
__global__ void __launch_bounds__(256, 1) k_main(const float* __restrict__ W,
                                                 const float* __restrict__ V,
                                                 const float* __restrict__ U,
                                                 float* __restrict__ dout,
                                                 int out_size) {
    extern __shared__ float sm[];
    float* r_s  = sm;            // 2 * 8192
    float* w_s  = sm + 16384;    // 4096
    float* part = sm + 20480;    // 24576
    float* y_s  = sm + 45056;    // 768
    const int tid = threadIdx.x;
    const int g0  = blockIdx.x * 4;

    // stage weights: per h: W rows g0..g0+3, then V0[h], V1[h]
#pragma unroll 2
    for (int h = tid; h < HDIM; h += 256) {
        w_s[h * 8 + 0] = W[(g0 + 0) * HDIM + h];
        w_s[h * 8 + 1] = W[(g0 + 1) * HDIM + h];
        w_s[h * 8 + 2] = W[(g0 + 2) * HDIM + h];
        w_s[h * 8 + 3] = W[(g0 + 3) * HDIM + h];
        w_s[h * 8 + 4] = V[h * 2 + 0];
        w_s[h * 8 + 5] = V[h * 2 + 1];
        w_s[h * 8 + 6] = 0.f;
        w_s[h * 8 + 7] = 0.f;
    }
    const int eg = tid >> 6;   // epilogue g (0..3)
    const int eb = tid & 63;   // epilogue b
    const float u0 = U[(g0 + eg) * 2 + 0];
    const float u1 = U[(g0 + eg) * 2 + 1];
    float v = 0.f;
    // zero r_0 slice owned by this CTA
    g_rbuf[(size_t)(g0 + eg) * BATCH + eb] = 0.f;
    grid_barrier();

    const int sl = tid >> 3;  // h-slice 0..31 (4 h per chunk)
    const int bg = tid & 7;   // batch-group: b in {4bg..4bg+3} U {32+4bg..35+4bg}
    const unsigned rb[2] = {smem_u32(r_s), smem_u32(r_s + 8192)};

    for (int t = 0; t < T_STEPS; ++t) {
        const float* rg = g_rbuf + (size_t)t * (HDIM * BATCH);
        // prefetch chunks 0,1 into ring buffers
#pragma unroll
        for (int c = 0; c < 2; ++c) {
#pragma unroll
            for (int k = 0; k < 8; ++k) {
                int i4 = k * 256 + tid;
                cp16(rb[c] + i4 * 16, rg + c * 8192 + i4 * 4);
            }
            cp_commit();
        }
        // early per-step scalar loads (hide L2 latency behind compute)
        const float xi = __ldg(&g_xin[(size_t)t * (HDIM * BATCH) + (g0 + eg) * BATCH + eb]);
        const float* sp = g_sbuf + ((size_t)t * BATCH + eb) * 2;
        const float s0 = __ldg(sp), s1 = __ldg(sp + 1);

        ull acc[12][4];
#pragma unroll
        for (int m = 0; m < 12; ++m)
#pragma unroll
            for (int j = 0; j < 4; ++j) acc[m][j] = 0ULL;

#pragma unroll
        for (int c = 0; c < 4; ++c) {
            if (c == 3) cp_wait<0>(); else cp_wait<1>();
            __syncthreads();
            const float* rc = r_s + (c & 1) * 8192;
            const float* wc = w_s + c * 128 * 8;
#pragma unroll
            for (int hh = 0; hh < 4; ++hh) {
                const int hl = sl * 4 + hh;
                const float4 w4 = *(const float4*)(wc + hl * 8);
                const float2 vv = *(const float2*)(wc + hl * 8 + 4);
                const ulonglong2 ra = *(const ulonglong2*)(rc + hl * 64 + bg * 4);
                const ulonglong2 rx = *(const ulonglong2*)(rc + hl * 64 + 32 + bg * 4);
                ull r[4] = {ra.x, ra.y, rx.x, rx.y};
                const ull v0d = dup2(vv.x), v1d = dup2(vv.y);
                ull w2[4] = {dup2(w4.x), dup2(w4.y), dup2(w4.z), dup2(w4.w)};
                ull rv0[4], rv1[4];
#pragma unroll
                for (int j = 0; j < 4; ++j) {
                    rv0[j] = fmul2(v0d, r[j]);
                    rv1[j] = fmul2(v1d, r[j]);
                }
#pragma unroll
                for (int g = 0; g < 4; ++g) {
#pragma unroll
                    for (int j = 0; j < 4; ++j) {
                        acc[g * 3 + 0][j] = ffma2(w2[g], r[j],   acc[g * 3 + 0][j]);
                        acc[g * 3 + 1][j] = ffma2(w2[g], rv0[j], acc[g * 3 + 1][j]);
                        acc[g * 3 + 2][j] = ffma2(w2[g], rv1[j], acc[g * 3 + 2][j]);
                    }
                }
            }
            __syncthreads();
            if (c < 2) {  // prefetch chunk c+2 into freed buffer
#pragma unroll
                for (int k = 0; k < 8; ++k) {
                    int i4 = k * 256 + tid;
                    cp16(rb[c] + i4 * 16, rg + (c + 2) * 8192 + i4 * 4);
                }
                cp_commit();
            }
        }

        // write partials (split-batch layout maps back to natural b)
        {
            float* pb = part + sl * 768;
#pragma unroll
            for (int row = 0; row < 12; ++row) {
                ulonglong2 pa, pc;
                pa.x = acc[row][0]; pa.y = acc[row][1];
                pc.x = acc[row][2]; pc.y = acc[row][3];
                *(ulonglong2*)(pb + row * 64 + bg * 4) = pa;
                *(ulonglong2*)(pb + row * 64 + 32 + bg * 4) = pc;
            }
        }
        __syncthreads();

        // reduce 32 slices -> y_s[12][64] (fixed order: deterministic)
        for (int item = tid; item < 384; item += 256) {
            const int row = item >> 5, bp = item & 31;
            const float* src = part + row * 64 + bp * 2;
            ull a0 = 0ULL, a1 = 0ULL, a2 = 0ULL, a3 = 0ULL;
#pragma unroll
            for (int s4 = 0; s4 < 32; s4 += 4) {
                a0 = fadd2(a0, *(const ull*)(src + (s4 + 0) * 768));
                a1 = fadd2(a1, *(const ull*)(src + (s4 + 1) * 768));
                a2 = fadd2(a2, *(const ull*)(src + (s4 + 2) * 768));
                a3 = fadd2(a3, *(const ull*)(src + (s4 + 3) * 768));
            }
            *(ull*)(y_s + row * 64 + bp * 2) = fadd2(fadd2(a0, a1), fadd2(a2, a3));
        }
        __syncthreads();

        // epilogue: v update, r store
        {
            const float y0 = y_s[(eg * 3 + 0) * 64 + eb];
            const float y1 = y_s[(eg * 3 + 1) * 64 + eb];
            const float y2 = y_s[(eg * 3 + 2) * 64 + eb];
            v = ONEMA * v + ALPHA * (y0 + s0 * u0 * y1 + s1 * u1 * y2 + xi);
            const float r = tanhf(v);
            g_rbuf[(size_t)(t + 1) * (HDIM * BATCH) + (g0 + eg) * BATCH + eb] = r;
            if (t == T_STEPS - 1 && out_size >= BATCH * T_STEPS + BATCH * HDIM)
                dout[BATCH * T_STEPS + eb * HDIM + (g0 + eg)] = v;  // vT
        }
        grid_barrier();
    }
}

// ---------------- k_out: y[b,t] = tanh(v_{t+1}) @ w_out + b_out -------------
__global__ void __launch_bounds__(256, 1) k_out(const float* __restrict__ wout,
                                                const float* __restrict__ bout,
                                                float* __restrict__ dout,
                                                int out_size) {
    __shared__ float w_sh[HDIM];
    const int tid = threadIdx.x;
    w_sh[tid] = wout[tid];
    w_sh[tid + 256] = wout[tid + 256];
    __syncthreads();
    int gid = blockIdx.x * 256 + tid;
    int b = gid & 63, t = gid >> 6;
    const float* rp = g_rbuf + (size_t)(t + 1) * (HDIM * BATCH) + b;
    float acc = bout[0];
#pragma unroll 8
    for (int g = 0; g < HDIM; ++g) acc = fmaf(rp[g * BATCH], w_sh[g], acc);
    int o = b * T_STEPS + t;
    if (o < out_size) dout[o] = acc;
}

// ---------------- launch -----------------------------------------------------
extern "C" void kernel_launch(void* const* d_in, const int* in_sizes, int n_in,
                              void* d_out, int out_size) {
    const float* x    = (const float*)d_in[0];
    const float* win  = (const float*)d_in[1];
    const float* wrec = (const float*)d_in[2];
    const float* brec = (const float*)d_in[3];
    const float* wout = (const float*)d_in[4];
    const float* bout = (const float*)d_in[5];
    const float* wzz  = (const float*)d_in[6];
    const float* bzz  = (const float*)d_in[7];
    const float* Bz   = (const float*)d_in[8];
    const float* M    = (const float*)d_in[9];
    const float* c    = (const float*)d_in[10];
    const float* U    = (const float*)d_in[11];
    const float* V    = (const float*)d_in[12];
    float* out = (float*)d_out;

    cudaFuncSetAttribute(k_xin,  cudaFuncAttributeMaxDynamicSharedMemorySize, 16384 * 4);
    cudaFuncSetAttribute(k_xz,   cudaFuncAttributeMaxDynamicSharedMemorySize, 12288 * 4);
    cudaFuncSetAttribute(k_main, cudaFuncAttributeMaxDynamicSharedMemorySize, 45824 * 4);

    k_xin<<<dim3(T_STEPS, HDIM / 64), 128, 16384 * 4>>>(x, win, brec);
    k_xz<<<T_STEPS, 64, 12288 * 4>>>(x, Bz, bzz);
    k_zscan<<<BATCH, 32>>>(wzz, M, c, out, out_size);
    k_main<<<GRID_MAIN, 256, 45824 * 4>>>(wrec, V, U, out, out_size);
    k_out<<<(BATCH * T_STEPS) / 256, 256>>>(wout, bout, out, out_size);
}

// round 7
// speedup vs baseline: 1.3712x; 1.0079x over previous
#include <cuda_runtime.h>

#define T_STEPS 512
#define BATCH   64
#define IDIM    128
#define HDIM    512
#define ZDIM    32
#define GRID_MAIN 128
#define ALPHA 0.2f
#define ONEMA 0.8f

typedef unsigned long long ull;

// ---------------- device scratch (static globals; no runtime allocation) ----
__device__ float g_xin [(size_t)T_STEPS * HDIM * BATCH];        // (t, g, b)
__device__ float g_rbuf[(size_t)(T_STEPS + 1) * HDIM * BATCH];  // (t, h, b)
__device__ float g_xz  [(size_t)T_STEPS * BATCH * ZDIM];        // (t, b, z)
__device__ float g_sbuf[(size_t)T_STEPS * BATCH * 2];           // (t, b, k): s-0.5
__device__ unsigned long long g_bar;                            // monotonic barrier

// ---------------- helpers ---------------------------------------------------
__device__ __forceinline__ unsigned smem_u32(const void* p) {
    return (unsigned)__cvta_generic_to_shared(p);
}
__device__ __forceinline__ void cp16(unsigned dst, const void* src) {
    asm volatile("cp.async.cg.shared.global [%0], [%1], 16;" :: "r"(dst), "l"(src));
}
__device__ __forceinline__ void cp_commit() {
    asm volatile("cp.async.commit_group;");
}
template <int N>
__device__ __forceinline__ void cp_wait() {
    asm volatile("cp.async.wait_group %0;" :: "n"(N));
}
// packed fp32x2 math (sm_100+)
__device__ __forceinline__ ull ffma2(ull a, ull b, ull c) {
    ull d; asm("fma.rn.f32x2 %0,%1,%2,%3;" : "=l"(d) : "l"(a), "l"(b), "l"(c)); return d;
}
__device__ __forceinline__ ull fmul2(ull a, ull b) {
    ull d; asm("mul.rn.f32x2 %0,%1,%2;" : "=l"(d) : "l"(a), "l"(b)); return d;
}
__device__ __forceinline__ ull fadd2(ull a, ull b) {
    ull d; asm("add.rn.f32x2 %0,%1,%2;" : "=l"(d) : "l"(a), "l"(b)); return d;
}
__device__ __forceinline__ ull dup2(float x) {
    ull d; asm("mov.b64 %0,{%1,%1};" : "=l"(d) : "f"(x)); return d;
}

// Replay-safe grid barrier: monotonic counter, target derived from arrival slot.
__device__ __forceinline__ void grid_barrier() {
    __syncthreads();
    if (threadIdx.x == 0) {
        __threadfence();
        unsigned long long a = atomicAdd(&g_bar, 1ULL);
        unsigned long long target = (a / GRID_MAIN + 1ULL) * (unsigned long long)GRID_MAIN;
        unsigned long long cur;
        do {
            asm volatile("ld.global.acquire.gpu.u64 %0, [%1];" : "=l"(cur) : "l"(&g_bar));
        } while (cur < target);
    }
    __syncthreads();
}

// ---------------- k_xin: xin[t,g,b] = sum_i x[b,t,i]*W_in[g,i] + b_rec[g] ----
// grid (T, H/64), 128 threads, 64KB dyn smem, f32x2 inner loop
__global__ void __launch_bounds__(128, 1) k_xin(const float* __restrict__ x,
                                                const float* __restrict__ win,
                                                const float* __restrict__ brec) {
    extern __shared__ float sm[];
    float* x_s = sm;         // [i][b]
    float* w_s = sm + 8192;  // [i][gl]
    const int tid = threadIdx.x;
    const int t   = blockIdx.x;
    const int g0  = blockIdx.y * 64;

    for (int idx = tid; idx < 8192; idx += 128) {
        int b = idx >> 7, i = idx & 127;
        x_s[i * 64 + b] = x[(size_t)b * (T_STEPS * IDIM) + t * IDIM + i];
    }
    for (int idx = tid; idx < 8192; idx += 128) {
        int gl = idx >> 7, i = idx & 127;
        w_s[i * 64 + gl] = win[(g0 + gl) * IDIM + i];
    }
    __syncthreads();

    const int gt = tid >> 3;   // 16 groups of 4 g
    const int bt = tid & 7;    // 8 groups of 8 b (4 packed pairs)
    ull acc[4][4];
#pragma unroll
    for (int a = 0; a < 4; ++a)
#pragma unroll
        for (int j = 0; j < 4; ++j) acc[a][j] = 0ULL;

    const float4* wp = (const float4*)w_s + gt;
    const ull* xp = (const ull*)x_s + bt * 4;
#pragma unroll 4
    for (int i = 0; i < 128; ++i) {
        float4 wv = wp[i * 16];
        ull x0 = xp[i * 32], x1 = xp[i * 32 + 1], x2 = xp[i * 32 + 2], x3 = xp[i * 32 + 3];
        ull w0 = dup2(wv.x), w1 = dup2(wv.y), w2 = dup2(wv.z), w3 = dup2(wv.w);
        acc[0][0] = ffma2(w0, x0, acc[0][0]); acc[0][1] = ffma2(w0, x1, acc[0][1]);
        acc[0][2] = ffma2(w0, x2, acc[0][2]); acc[0][3] = ffma2(w0, x3, acc[0][3]);
        acc[1][0] = ffma2(w1, x0, acc[1][0]); acc[1][1] = ffma2(w1, x1, acc[1][1]);
        acc[1][2] = ffma2(w1, x2, acc[1][2]); acc[1][3] = ffma2(w1, x3, acc[1][3]);
        acc[2][0] = ffma2(w2, x0, acc[2][0]); acc[2][1] = ffma2(w2, x1, acc[2][1]);
        acc[2][2] = ffma2(w2, x2, acc[2][2]); acc[2][3] = ffma2(w2, x3, acc[2][3]);
        acc[3][0] = ffma2(w3, x0, acc[3][0]); acc[3][1] = ffma2(w3, x1, acc[3][1]);
        acc[3][2] = ffma2(w3, x2, acc[3][2]); acc[3][3] = ffma2(w3, x3, acc[3][3]);
    }
#pragma unroll
    for (int a = 0; a < 4; ++a) {
        int g = g0 + gt * 4 + a;
        ull bias = dup2(brec[g]);
        ull* op = (ull*)(g_xin + (size_t)t * (HDIM * BATCH) + g * BATCH + bt * 8);
#pragma unroll
        for (int j = 0; j < 4; ++j) op[j] = fadd2(acc[a][j], bias);
    }
}

// ---------------- k_xz: xz[t,b,z] = sum_i x[b,t,i]*B_z[z,i] + b_zz[z] -------
__global__ void __launch_bounds__(64, 1) k_xz(const float* __restrict__ x,
                                              const float* __restrict__ Bz,
                                              const float* __restrict__ bzz) {
    extern __shared__ float sm[];
    float* x_s  = sm;         // [i][b]
    float* bz_s = sm + 8192;  // [i][z]
    const int tid = threadIdx.x;
    const int t   = blockIdx.x;

    for (int idx = tid; idx < 8192; idx += 64) {
        int b = idx >> 7, i = idx & 127;
        x_s[i * 64 + b] = x[(size_t)b * (T_STEPS * IDIM) + t * IDIM + i];
    }
    for (int idx = tid; idx < 4096; idx += 64) {
        int z = idx >> 7, i = idx & 127;
        bz_s[i * 32 + z] = Bz[z * IDIM + i];
    }
    __syncthreads();

    const int zt = tid >> 3;
    const int bt = tid & 7;
    float acc[4][8];
#pragma unroll
    for (int a = 0; a < 4; ++a)
#pragma unroll
        for (int j = 0; j < 8; ++j) acc[a][j] = 0.f;

    const float4* wp = (const float4*)bz_s + zt;
    const float4* xp = (const float4*)x_s + bt * 2;
#pragma unroll 4
    for (int i = 0; i < 128; ++i) {
        float4 wv = wp[i * 8];
        float4 xa = xp[i * 16];
        float4 xb = xp[i * 16 + 1];
        float xv[8] = {xa.x, xa.y, xa.z, xa.w, xb.x, xb.y, xb.z, xb.w};
#pragma unroll
        for (int j = 0; j < 8; ++j) {
            acc[0][j] = fmaf(wv.x, xv[j], acc[0][j]);
            acc[1][j] = fmaf(wv.y, xv[j], acc[1][j]);
            acc[2][j] = fmaf(wv.z, xv[j], acc[2][j]);
            acc[3][j] = fmaf(wv.w, xv[j], acc[3][j]);
        }
    }
#pragma unroll
    for (int a = 0; a < 4; ++a) {
        int z = zt * 4 + a;
        float bias = bzz[z];
#pragma unroll
        for (int j = 0; j < 8; ++j) {
            int b = bt * 8 + j;
            g_xz[(size_t)t * (BATCH * ZDIM) + b * ZDIM + z] = acc[a][j] + bias;
        }
    }
}

// ---------------- k_zscan: sequential z recursion, emits (s-0.5) ------------
__global__ void k_zscan(const float* __restrict__ Wzz,
                        const float* __restrict__ M,
                        const float* __restrict__ c,
                        float* __restrict__ dout, int out_size) {
    __shared__ float wzz_s[ZDIM * ZDIM];  // transposed [j][i]
    __shared__ float fzs[ZDIM];
    const int i = threadIdx.x;
    const int b = blockIdx.x;

    for (int idx = i; idx < ZDIM * ZDIM; idx += 32) {
        int is = idx >> 5, j = idx & 31;
        wzz_s[j * 32 + is] = Wzz[idx];
    }
    float m0 = M[i], m1 = M[ZDIM + i];
    float c0 = c[0], c1 = c[1];
    float z = 0.f;
    __syncwarp();

    for (int t = 0; t < T_STEPS; ++t) {
        fzs[i] = tanhf(z);
        __syncwarp();
        float a = 0.f;
#pragma unroll 8
        for (int j = 0; j < 32; ++j) a = fmaf(wzz_s[j * 32 + i], fzs[j], a);
        __syncwarp();
        z = ONEMA * z + ALPHA * (a + g_xz[(size_t)t * (BATCH * ZDIM) + b * ZDIM + i]);
        float p0 = m0 * z, p1 = m1 * z;
#pragma unroll
        for (int off = 16; off; off >>= 1) {
            p0 += __shfl_xor_sync(0xffffffffu, p0, off);
            p1 += __shfl_xor_sync(0xffffffffu, p1, off);
        }
        if (i == 0) {
            size_t o = ((size_t)t * BATCH + b) * 2;
            g_sbuf[o + 0] = 1.f / (1.f + expf(-(p0 + c0))) - 0.5f;
            g_sbuf[o + 1] = 1.f / (1.f + expf(-(p1 + c1))) - 0.5f;
        }
    }
    if (out_size >= BATCH * T_STEPS + BATCH * HDIM + BATCH * ZDIM)
        dout[BATCH * T_STEPS + BATCH * HDIM + b * ZDIM + i] = z;  // zT
}

// ---------------- k_main: persistent recurrent core -------------------------
// grid 128, 512 threads, dyn smem = 51968 floats (207,872 B)
// SMEM: r_s[512h][64b] (full r_t, 128KB) | wd[512h][12] (dup-packed weights) |
//       part[16 sl][12 row][64 b] | y_s[12][64]
__global__ void __launch_bounds__(512, 1) k_main(const float* __restrict__ W,
                                                 const float* __restrict__ V,
                                                 const float* __restrict__ U,
                                                 float* __restrict__ dout,
                                                 int out_size) {
    extern __shared__ float sm[];
    float* r_s  = sm;            // 32768
    float* wd   = sm + 32768;    // 6144
    float* part = sm + 38912;    // 12288
    float* y_s  = sm + 51200;    // 768
    const int tid = threadIdx.x;
    const int g0  = blockIdx.x * 4;

    // stage duplicated packed weights: per h {w0,w0,w1,w1,w2,w2,w3,w3,v0,v0,v1,v1}
    {
        const int h = tid;  // 512 threads, 512 h
        float w0 = W[(g0 + 0) * HDIM + h];
        float w1 = W[(g0 + 1) * HDIM + h];
        float w2 = W[(g0 + 2) * HDIM + h];
        float w3 = W[(g0 + 3) * HDIM + h];
        float v0 = V[h * 2 + 0], v1 = V[h * 2 + 1];
        float* p = wd + h * 12;
        p[0] = w0; p[1] = w0; p[2]  = w1; p[3]  = w1;
        p[4] = w2; p[5] = w2; p[6]  = w3; p[7]  = w3;
        p[8] = v0; p[9] = v0; p[10] = v1; p[11] = v1;
    }
    const int eg = tid >> 6;  // epilogue g (valid for tid<256)
    const int eb = tid & 63;
    float u0 = 0.f, u1 = 0.f, v = 0.f;
    if (tid < 256) {
        u0 = U[(g0 + eg) * 2 + 0];
        u1 = U[(g0 + eg) * 2 + 1];
        g_rbuf[(size_t)(g0 + eg) * BATCH + eb] = 0.f;  // r_0 = tanh(0)
    }
    grid_barrier();

    const int sl = tid >> 5;  // h-slice 0..15 (warp-uniform)
    const int bg = tid & 31;  // batch pair b = {2bg, 2bg+1}
    const unsigned rbase = smem_u32(r_s);

    for (int t = 0; t < T_STEPS; ++t) {
        const float* rg = g_rbuf + (size_t)t * (HDIM * BATCH);
        // issue all 4 chunk groups up front (no buffer reuse -> no tail syncs)
#pragma unroll
        for (int c = 0; c < 4; ++c) {
#pragma unroll
            for (int k = 0; k < 4; ++k) {
                int i4 = c * 2048 + k * 512 + tid;
                cp16(rbase + i4 * 16, rg + i4 * 4);
            }
            cp_commit();
        }
        // per-step scalars (hide L2 latency behind chunk 0 wait)
        float xi = 0.f, s0 = 0.f, s1 = 0.f;
        if (tid < 256) {
            xi = __ldg(&g_xin[(size_t)t * (HDIM * BATCH) + (g0 + eg) * BATCH + eb]);
            const float* sp = g_sbuf + ((size_t)t * BATCH + eb) * 2;
            s0 = __ldg(sp); s1 = __ldg(sp + 1);
        }

        ull acc[12];
#pragma unroll
        for (int m = 0; m < 12; ++m) acc[m] = 0ULL;

#pragma unroll
        for (int c = 0; c < 4; ++c) {
            if (c == 0) cp_wait<3>();
            else if (c == 1) cp_wait<2>();
            else if (c == 2) cp_wait<1>();
            else cp_wait<0>();
            __syncthreads();
#pragma unroll
            for (int hh = 0; hh < 8; ++hh) {
                const int h = (c * 8 + hh) * 16 + sl;
                const float* wp = wd + h * 12;
                const ulonglong2 wab = *(const ulonglong2*)(wp);      // w0d, w1d
                const ulonglong2 wcd = *(const ulonglong2*)(wp + 4);  // w2d, w3d
                const ulonglong2 vvd = *(const ulonglong2*)(wp + 8);  // v0d, v1d
                const ull r = *(const ull*)(r_s + h * 64 + bg * 2);
                const ull rv0 = fmul2(vvd.x, r);
                const ull rv1 = fmul2(vvd.y, r);
                acc[0]  = ffma2(wab.x, r,   acc[0]);
                acc[1]  = ffma2(wab.x, rv0, acc[1]);
                acc[2]  = ffma2(wab.x, rv1, acc[2]);
                acc[3]  = ffma2(wab.y, r,   acc[3]);
                acc[4]  = ffma2(wab.y, rv0, acc[4]);
                acc[5]  = ffma2(wab.y, rv1, acc[5]);
                acc[6]  = ffma2(wcd.x, r,   acc[6]);
                acc[7]  = ffma2(wcd.x, rv0, acc[7]);
                acc[8]  = ffma2(wcd.x, rv1, acc[8]);
                acc[9]  = ffma2(wcd.y, r,   acc[9]);
                acc[10] = ffma2(wcd.y, rv0, acc[10]);
                acc[11] = ffma2(wcd.y, rv1, acc[11]);
            }
        }

        // write partials: part[sl][row][b]
        {
            float* pb = part + sl * 768 + bg * 2;
#pragma unroll
            for (int row = 0; row < 12; ++row) *(ull*)(pb + row * 64) = acc[row];
        }
        __syncthreads();

        // reduce 16 slices -> y_s[12][64] (12 warps, fixed order)
        if (tid < 384) {
            const int row = tid >> 5, bp = tid & 31;
            const float* src = part + row * 64 + bp * 2;
            ull a0 = 0ULL, a1 = 0ULL, a2 = 0ULL, a3 = 0ULL;
#pragma unroll
            for (int s4 = 0; s4 < 16; s4 += 4) {
                a0 = fadd2(a0, *(const ull*)(src + (s4 + 0) * 768));
                a1 = fadd2(a1, *(const ull*)(src + (s4 + 1) * 768));
                a2 = fadd2(a2, *(const ull*)(src + (s4 + 2) * 768));
                a3 = fadd2(a3, *(const ull*)(src + (s4 + 3) * 768));
            }
            *(ull*)(y_s + row * 64 + bp * 2) = fadd2(fadd2(a0, a1), fadd2(a2, a3));
        }
        __syncthreads();

        // epilogue: v update, r store (threads 0..255 own (g, b) pairs)
        if (tid < 256) {
            const float y0 = y_s[(eg * 3 + 0) * 64 + eb];
            const float y1 = y_s[(eg * 3 + 1) * 64 + eb];
            const float y2 = y_s[(eg * 3 + 2) * 64 + eb];
            v = ONEMA * v + ALPHA * (y0 + s0 * u0 * y1 + s1 * u1 * y2 + xi);
            const float r = tanhf(v);
            g_rbuf[(size_t)(t + 1) * (HDIM * BATCH) + (g0 + eg) * BATCH + eb] = r;
            if (t == T_STEPS - 1 && out_size >= BATCH * T_STEPS + BATCH * HDIM)
                dout[BATCH * T_STEPS + eb * HDIM + (g0 + eg)] = v;  // vT
        }
        grid_barrier();
    }
}

// ---------------- k_out: y[b,t] = tanh(v_{t+1}) @ w_out + b_out -------------
__global__ void __launch_bounds__(256, 1) k_out(const float* __restrict__ wout,
                                                const float* __restrict__ bout,
                                                float* __restrict__ dout,
                                                int out_size) {
    __shared__ float w_sh[HDIM];
    const int tid = threadIdx.x;
    w_sh[tid] = wout[tid];
    w_sh[tid + 256] = wout[tid + 256];
    __syncthreads();
    int gid = blockIdx.x * 256 + tid;
    int b = gid & 63, t = gid >> 6;
    const float* rp = g_rbuf + (size_t)(t + 1) * (HDIM * BATCH) + b;
    float acc = bout[0];
#pragma unroll 8
    for (int g = 0; g < HDIM; ++g) acc = fmaf(rp[g * BATCH], w_sh[g], acc);
    int o = b * T_STEPS + t;
    if (o < out_size) dout[o] = acc;
}

// ---------------- launch -----------------------------------------------------
extern "C" void kernel_launch(void* const* d_in, const int* in_sizes, int n_in,
                              void* d_out, int out_size) {
    const float* x    = (const float*)d_in[0];
    const float* win  = (const float*)d_in[1];
    const float* wrec = (const float*)d_in[2];
    const float* brec = (const float*)d_in[3];
    const float* wout = (const float*)d_in[4];
    const float* bout = (const float*)d_in[5];
    const float* wzz  = (const float*)d_in[6];
    const float* bzz  = (const float*)d_in[7];
    const float* Bz   = (const float*)d_in[8];
    const float* M    = (const float*)d_in[9];
    const float* c    = (const float*)d_in[10];
    const float* U    = (const float*)d_in[11];
    const float* V    = (const float*)d_in[12];
    float* out = (float*)d_out;

    cudaFuncSetAttribute(k_xin,  cudaFuncAttributeMaxDynamicSharedMemorySize, 16384 * 4);
    cudaFuncSetAttribute(k_xz,   cudaFuncAttributeMaxDynamicSharedMemorySize, 12288 * 4);
    cudaFuncSetAttribute(k_main, cudaFuncAttributeMaxDynamicSharedMemorySize, 51968 * 4);

    k_xin<<<dim3(T_STEPS, HDIM / 64), 128, 16384 * 4>>>(x, win, brec);
    k_xz<<<T_STEPS, 64, 12288 * 4>>>(x, Bz, bzz);
    k_zscan<<<BATCH, 32>>>(wzz, M, c, out, out_size);
    k_main<<<GRID_MAIN, 512, 51968 * 4>>>(wrec, V, U, out, out_size);
    k_out<<<(BATCH * T_STEPS) / 256, 256>>>(wout, bout, out, out_size);
}